// round 16
// baseline (speedup 1.0000x reference)
#include <cuda_runtime.h>
#include <cuda_fp16.h>
#include <math.h>
#include <stdint.h>

// Problem constants
constexpr int CB = 2;      // batch
constexpr int CT = 4096;   // seq len
constexpr int CD = 1024;   // d_model
constexpr int CL = 2;      // layers
constexpr int CH = 16;     // heads
constexpr int CF = 4096;   // d_ff
constexpr int CK = 2048;   // top-k tokens
constexpr int BK_ROWS = CB * CK;
constexpr size_t BTD = (size_t)CB * CT * CD;

// Weight fp16 scratch offsets (elements)
constexpr size_t WQKV_OFF = 0;
constexpr size_t WQKV_SZ  = (size_t)CL * CD * 3 * CD;
constexpr size_t WO_OFF   = WQKV_OFF + WQKV_SZ;
constexpr size_t WO_SZ    = (size_t)CL * CD * CD;
constexpr size_t W1_OFF   = WO_OFF + WO_SZ;
constexpr size_t W1_SZ    = (size_t)CL * CD * CF;
constexpr size_t W2_OFF   = W1_OFF + W1_SZ;
constexpr size_t W2_SZ    = (size_t)CL * CF * CD;
constexpr size_t WTF_TOTAL = W2_OFF + W2_SZ;

// ---------------- scratch (static device globals) ---------------------------
__device__ float  g_logits[CB * CT];
__device__ int    g_sel[CB * CT];
__device__ int    g_idx[CB * CK];
__device__ int    g_inv[CB * CT];
__device__ float  g_gate[CB * CK];
__device__ float  g_h[BK_ROWS * CD];
__device__ __half g_lnh[BK_ROWS * CD];
__device__ __half g_qkvh[(size_t)BK_ROWS * 3 * CD];
__device__ __half g_attnh[BK_ROWS * CD];
__device__ __half g_midh[(size_t)BK_ROWS * CF];
__device__ __half g_wth[WTF_TOTAL];

__device__ __forceinline__ void mma_f16(float c[4], const uint32_t a[4],
                                        uint32_t b0, uint32_t b1) {
    asm volatile(
        "mma.sync.aligned.m16n8k16.row.col.f32.f16.f16.f32 "
        "{%0,%1,%2,%3}, {%4,%5,%6,%7}, {%8,%9}, {%0,%1,%2,%3};\n"
        : "+f"(c[0]), "+f"(c[1]), "+f"(c[2]), "+f"(c[3])
        : "r"(a[0]), "r"(a[1]), "r"(a[2]), "r"(a[3]), "r"(b0), "r"(b1));
}
__device__ __forceinline__ void ldsm_x4(uint32_t r[4], uint32_t saddr) {
    asm volatile("ldmatrix.sync.aligned.m8n8.x4.shared.b16 {%0,%1,%2,%3}, [%4];"
                 : "=r"(r[0]), "=r"(r[1]), "=r"(r[2]), "=r"(r[3]) : "r"(saddr));
}
__device__ __forceinline__ void ldsm_x4t(uint32_t r[4], uint32_t saddr) {
    asm volatile("ldmatrix.sync.aligned.m8n8.x4.trans.shared.b16 {%0,%1,%2,%3}, [%4];"
                 : "=r"(r[0]), "=r"(r[1]), "=r"(r[2]), "=r"(r[3]) : "r"(saddr));
}
__device__ __forceinline__ void cp16(uint32_t dst, const void* src) {
    asm volatile("cp.async.cg.shared.global [%0], [%1], 16;\n" :: "r"(dst), "l"(src));
}
__device__ __forceinline__ uint32_t pack_h2(float a, float b) {
    __half2 h = __floats2half2_rn(a, b);
    return *(uint32_t*)&h;
}

// ---------------- kernel A: WQKV convert + router ----------------------------
constexpr int QCVT_THREADS = (int)(WQKV_SZ / 16);          // 393216 (4 float4/thr)
constexpr int QCVT_BLOCKS = QCVT_THREADS / 256;            // 1536
constexpr int ROUTER_BLOCKS = (CB * CT) / 8;               // 1024

__global__ void cvtq_router_kernel(const float* __restrict__ wqkv,
                                   __half* __restrict__ dst,
                                   const float* __restrict__ x,
                                   const float* __restrict__ wr,
                                   const float* __restrict__ br,
                                   float* __restrict__ logits) {
    if (blockIdx.x < QCVT_BLOCKS) {
        const size_t stride = (size_t)QCVT_THREADS;
        size_t i0 = (size_t)blockIdx.x * 256 + threadIdx.x;
        __half2* d2 = (__half2*)(dst + WQKV_OFF);
#pragma unroll
        for (int j = 0; j < 4; j++) {
            size_t i = i0 + (size_t)j * stride;
            float4 v = ((const float4*)wqkv)[i];
            d2[2 * i]     = __floats2half2_rn(v.x, v.y);
            d2[2 * i + 1] = __floats2half2_rn(v.z, v.w);
        }
    } else {
        int gw = (((int)blockIdx.x - QCVT_BLOCKS) * 256 + (int)threadIdx.x) >> 5;
        if (gw >= CB * CT) return;
        int lane = threadIdx.x & 31;
        const float4* p = (const float4*)(x + (size_t)gw * CD);
        const float4* w4 = (const float4*)wr;
        float s = 0.f;
#pragma unroll
        for (int i = 0; i < CD / 128; i++) {
            float4 a = p[lane + i * 32];
            float4 w = w4[lane + i * 32];
            s += a.x * w.x + a.y * w.y + a.z * w.z + a.w * w.w;
        }
#pragma unroll
        for (int o = 16; o > 0; o >>= 1) s += __shfl_down_sync(0xffffffffu, s, o);
        if (lane == 0) logits[gw] = s + br[0];
    }
}

// ---------------- top-K -----------------------------------------------------
__global__ void rank_kernel(const float* __restrict__ logits, int* __restrict__ sel) {
    int blk = blockIdx.x;
    int b = blk >> 6;
    int base = (blk & 63) * 64;
    __shared__ float lv[CT];
    int tid = threadIdx.x;
    for (int t = tid; t < CT; t += 256) lv[t] = logits[b * CT + t];
    __syncthreads();
    int tt = tid >> 2, part = tid & 3;
    int t = base + tt;
    float v = lv[t];
    int cnt = 0;
    int s0 = part * 1024;
#pragma unroll 8
    for (int s = s0; s < s0 + 1024; s++) {
        float u = lv[s];
        cnt += (u > v) || (u == v && s < t);
    }
    __shared__ int rk[64];
    if (part == 0) rk[tt] = 0;
    __syncthreads();
    atomicAdd(&rk[tt], cnt);
    __syncthreads();
    if (part == 0) sel[b * CT + t] = (rk[tt] < CK) ? 1 : 0;
}

__global__ void compact_kernel(const float* __restrict__ logits,
                               const int* __restrict__ sel,
                               int* __restrict__ idx_out,
                               int* __restrict__ inv_out,
                               float* __restrict__ gate_out) {
    int b = blockIdx.x;
    int tid = threadIdx.x;
    int f[4]; int c = 0;
#pragma unroll
    for (int i = 0; i < 4; i++) { f[i] = sel[b * CT + tid * 4 + i]; c += f[i]; }
    int lane = tid & 31, wid = tid >> 5;
    int incl = c;
#pragma unroll
    for (int o = 1; o < 32; o <<= 1) {
        int n = __shfl_up_sync(0xffffffffu, incl, o);
        if (lane >= o) incl += n;
    }
    __shared__ int wsum[32];
    if (lane == 31) wsum[wid] = incl;
    __syncthreads();
    if (wid == 0) {
        int w = wsum[lane];
#pragma unroll
        for (int o = 1; o < 32; o <<= 1) {
            int n = __shfl_up_sync(0xffffffffu, w, o);
            if (lane >= o) w += n;
        }
        wsum[lane] = w;
    }
    __syncthreads();
    int pos = (wid ? wsum[wid - 1] : 0) + incl - c;
#pragma unroll
    for (int i = 0; i < 4; i++) {
        int t = tid * 4 + i;
        if (f[i]) {
            idx_out[b * CK + pos] = t;
            inv_out[b * CT + t] = pos;
            float lg = logits[b * CT + t];
            gate_out[b * CK + pos] = 1.f / (1.f + expf(-lg));
            pos++;
        } else {
            inv_out[b * CT + t] = -1;
        }
    }
}

// ---------------- warp-per-row LN core ---------------------------------------
__device__ __forceinline__ void warp_ln_row(const float4 v[8], int lane,
                                            const float* __restrict__ scale,
                                            const float* __restrict__ bias,
                                            __half* __restrict__ outrow) {
    float s = 0.f, ss = 0.f;
#pragma unroll
    for (int j = 0; j < 8; j++) {
        s  += v[j].x + v[j].y + v[j].z + v[j].w;
        ss += v[j].x * v[j].x + v[j].y * v[j].y + v[j].z * v[j].z + v[j].w * v[j].w;
    }
#pragma unroll
    for (int o = 16; o > 0; o >>= 1) {
        s  += __shfl_xor_sync(0xffffffffu, s, o);
        ss += __shfl_xor_sync(0xffffffffu, ss, o);
    }
    float mean = s * (1.f / CD);
    float var = ss * (1.f / CD) - mean * mean;
    float inv = rsqrtf(var + 1e-5f);
#pragma unroll
    for (int j = 0; j < 8; j++) {
        int c4 = lane + 32 * j;
        float4 sc = ((const float4*)scale)[c4];
        float4 bi = ((const float4*)bias)[c4];
        __half2 h0 = __floats2half2_rn((v[j].x - mean) * inv * sc.x + bi.x,
                                       (v[j].y - mean) * inv * sc.y + bi.y);
        __half2 h1 = __floats2half2_rn((v[j].z - mean) * inv * sc.z + bi.z,
                                       (v[j].w - mean) * inv * sc.w + bi.w);
        __half2* o2 = (__half2*)outrow;
        o2[2 * c4]     = h0;
        o2[2 * c4 + 1] = h1;
    }
}

// ---------------- kernel B: gather+LN1 fused with Wo/W1/W2 convert -----------
constexpr int GLN_BLOCKS = BK_ROWS / 8;                    // 512
constexpr size_t RWCVT_SZ = WO_SZ + W1_SZ + W2_SZ;         // 18874368 elems
constexpr int RWCVT_THREADS = (int)(RWCVT_SZ / 16);        // 1179648
constexpr int RWCVT_BLOCKS = RWCVT_THREADS / 256;          // 4608

__global__ void gatherln_cvt_kernel(const float* __restrict__ x,
                                    const int* __restrict__ idx,
                                    const float* __restrict__ scale,
                                    const float* __restrict__ bias,
                                    float* __restrict__ h, __half* __restrict__ lnh,
                                    const float* __restrict__ wo,
                                    const float* __restrict__ w1,
                                    const float* __restrict__ w2,
                                    __half* __restrict__ wdst) {
    if (blockIdx.x < GLN_BLOCKS) {
        int bk = blockIdx.x * 8 + (threadIdx.x >> 5);
        int lane = threadIdx.x & 31;
        int b = bk >> 11;
        int t = idx[bk];
        const float4* src = (const float4*)(x + ((size_t)b * CT + t) * CD);
        float4* hdst = (float4*)(h + (size_t)bk * CD);
        float4 v[8];
#pragma unroll
        for (int j = 0; j < 8; j++) {
            v[j] = src[lane + 32 * j];
            hdst[lane + 32 * j] = v[j];
        }
        warp_ln_row(v, lane, scale, bias, lnh + (size_t)bk * CD);
    } else {
        constexpr size_t O4 = WO_SZ / 4, A4 = W1_SZ / 4;
        const size_t stride = (size_t)RWCVT_THREADS;
        size_t i0 = (size_t)(blockIdx.x - GLN_BLOCKS) * 256 + threadIdx.x;
        __half2* d2 = (__half2*)(wdst + WO_OFF);   // contiguous wo|w1|w2 region
#pragma unroll
        for (int j = 0; j < 4; j++) {
            size_t i = i0 + (size_t)j * stride;
            float4 v;
            if (i < O4)           v = ((const float4*)wo)[i];
            else if (i < O4 + A4) v = ((const float4*)w1)[i - O4];
            else                  v = ((const float4*)w2)[i - O4 - A4];
            d2[2 * i]     = __floats2half2_rn(v.x, v.y);
            d2[2 * i + 1] = __floats2half2_rn(v.z, v.w);
        }
    }
}

// ---------------- layernorm (warp-per-row, fp32 in -> fp16 out) --------------
__global__ void layernorm_kernel(const float* __restrict__ in, __half* __restrict__ out,
                                 const float* __restrict__ scale,
                                 const float* __restrict__ bias) {
    int row = blockIdx.x * 8 + (threadIdx.x >> 5);
    int lane = threadIdx.x & 31;
    const float4* p = (const float4*)(in + (size_t)row * CD);
    float4 v[8];
#pragma unroll
    for (int j = 0; j < 8; j++) v[j] = p[lane + 32 * j];
    warp_ln_row(v, lane, scale, bias, out + (size_t)row * CD);
}

// ---------------- common GEMM bits -------------------------------------------
__device__ __forceinline__ float gelu_tanh(float x) {
    float x3 = x * x * x;
    float t = tanhf(0.7978845608028654f * (x + 0.044715f * x3));
    return 0.5f * x * (1.f + t);
}

// ============ narrow GEMM: 128x128x64, 3-stage, issue->wait->sync->compute->sync
constexpr int GBM = 128, GBN = 128, GBK = 64;
constexpr int AST = GBK + 8;
constexpr int BST = GBN + 8;
constexpr int ABUFH = GBM * AST;
constexpr int BBUFH = GBK * BST;
constexpr size_t TGEMM_SMEM = (size_t)(ABUFH + BBUFH) * 3 * sizeof(__half);

__global__ __launch_bounds__(256) void tgemm_kernel(
    const __half* __restrict__ A, const __half* __restrict__ W,
    const float* __restrict__ bias, const float* __restrict__ R,
    float* __restrict__ C, int M, int N, int Kd) {
    extern __shared__ __half dsm[];
    __half* As = dsm;
    __half* Bs = dsm + 3 * ABUFH;

    const int tid = threadIdx.x;
    const int bx = blockIdx.x, by = blockIdx.y;
    const int wid = tid >> 5, lane = tid & 31;
    const int warp_m = wid & 1;
    const int warp_n = wid >> 1;
    const int g = lane >> 2;
    const int tg = lane & 3;
    const int lm = (lane & 7) + ((lane >> 3) & 1) * 8;
    const int lk = ((lane >> 4) & 1) * 8;
    const int vrow = (lane & 7) + ((lane >> 3) & 1) * 8;
    const int vcol = ((lane >> 4) & 1) * 8;

    float c[4][4][4];
#pragma unroll
    for (int mi = 0; mi < 4; mi++)
#pragma unroll
        for (int ni = 0; ni < 4; ni++)
#pragma unroll
            for (int r = 0; r < 4; r++) c[mi][ni][r] = 0.f;

    const int ntiles = Kd / GBK;

    auto issue_tile = [&](int t, int buf) {
        int k0 = t * GBK;
        uint32_t abase = (uint32_t)__cvta_generic_to_shared(As + buf * ABUFH);
        uint32_t bbase = (uint32_t)__cvta_generic_to_shared(Bs + buf * BBUFH);
#pragma unroll
        for (int i = 0; i < 4; i++) {
            int q = tid + i * 256;
            int row = q >> 3, c8 = (q & 7) * 8;
            cp16(abase + (row * AST + c8) * 2, A + (size_t)(by * GBM + row) * Kd + k0 + c8);
        }
#pragma unroll
        for (int i = 0; i < 4; i++) {
            int q = tid + i * 256;
            int row = q >> 4, n8 = (q & 15) * 8;
            cp16(bbase + (row * BST + n8) * 2, W + (size_t)(k0 + row) * N + bx * GBN + n8);
        }
        asm volatile("cp.async.commit_group;\n");
    };

    issue_tile(0, 0);
    if (ntiles > 1) issue_tile(1, 1);
    for (int t = 0; t < ntiles; t++) {
        if (t + 2 < ntiles) {
            issue_tile(t + 2, (t + 2) % 3);
            asm volatile("cp.async.wait_group 2;\n");
        } else if (t + 1 < ntiles) {
            asm volatile("cp.async.wait_group 1;\n");
        } else {
            asm volatile("cp.async.wait_group 0;\n");
        }
        __syncthreads();
        int buf = t % 3;
        uint32_t Ab = (uint32_t)__cvta_generic_to_shared(As + buf * ABUFH);
        uint32_t Bb = (uint32_t)__cvta_generic_to_shared(Bs + buf * BBUFH);
        uint32_t a_off = Ab + ((warp_m * 64 + lm) * AST + lk) * 2;
#pragma unroll
        for (int ks = 0; ks < GBK / 16; ks++) {
            uint32_t a[4][4], b[4][2];
#pragma unroll
            for (int mi = 0; mi < 4; mi++)
                ldsm_x4(a[mi], a_off + (mi * 16 * AST + ks * 16) * 2);
#pragma unroll
            for (int ni = 0; ni < 4; ni += 2) {
                uint32_t b4[4];
                ldsm_x4t(b4, Bb + ((ks * 16 + vrow) * BST + warp_n * 32 + ni * 8 + vcol) * 2);
                b[ni][0] = b4[0]; b[ni][1] = b4[1];
                b[ni + 1][0] = b4[2]; b[ni + 1][1] = b4[3];
            }
#pragma unroll
            for (int mi = 0; mi < 4; mi++)
#pragma unroll
                for (int ni = 0; ni < 4; ni++)
                    mma_f16(c[mi][ni], a[mi], b[ni][0], b[ni][1]);
        }
        __syncthreads();
    }

#pragma unroll
    for (int mi = 0; mi < 4; mi++) {
        int m0 = by * GBM + warp_m * 64 + mi * 16 + g;
#pragma unroll
        for (int ni = 0; ni < 4; ni++) {
            int n0 = bx * GBN + warp_n * 32 + ni * 8 + 2 * tg;
            float b0 = bias[n0], b1 = bias[n0 + 1];
#pragma unroll
            for (int half = 0; half < 2; half++) {
                int m = m0 + half * 8;
                float v0 = c[mi][ni][half * 2 + 0] + b0;
                float v1 = c[mi][ni][half * 2 + 1] + b1;
                const float2 r2 = *(const float2*)(R + (size_t)m * N + n0);
                v0 += r2.x; v1 += r2.y;
                *(float2*)(C + (size_t)m * N + n0) = make_float2(v0, v1);
            }
        }
    }
}

// ============ wide GEMM: 128x256x64, 4-buffer ring p=2, SINGLE sync/iter ====
constexpr int WBN = 256;
constexpr int BSTW = WBN + 8;
constexpr int BBUFW = GBK * BSTW;
constexpr size_t TGEMW_SMEM = (size_t)(ABUFH + BBUFW) * 4 * sizeof(__half);

template <bool GELU>
__global__ __launch_bounds__(256) void tgemm_wide(
    const __half* __restrict__ A, const __half* __restrict__ W,
    const float* __restrict__ bias, __half* __restrict__ C,
    int M, int N, int Kd) {
    extern __shared__ __half dsm[];
    __half* As = dsm;
    __half* Bs = dsm + 4 * ABUFH;

    const int tid = threadIdx.x;
    const int bx = blockIdx.x, by = blockIdx.y;
    const int wid = tid >> 5, lane = tid & 31;
    const int warp_m = wid & 1;
    const int warp_n = wid >> 1;
    const int g = lane >> 2;
    const int tg = lane & 3;
    const int lm = (lane & 7) + ((lane >> 3) & 1) * 8;
    const int lk = ((lane >> 4) & 1) * 8;
    const int vrow = (lane & 7) + ((lane >> 3) & 1) * 8;
    const int vcol = ((lane >> 4) & 1) * 8;

    float c[4][8][4];
#pragma unroll
    for (int mi = 0; mi < 4; mi++)
#pragma unroll
        for (int ni = 0; ni < 8; ni++)
#pragma unroll
            for (int r = 0; r < 4; r++) c[mi][ni][r] = 0.f;

    const int ntiles = Kd / GBK;

    auto issue_tile = [&](int t, int buf) {
        int k0 = t * GBK;
        uint32_t abase = (uint32_t)__cvta_generic_to_shared(As + buf * ABUFH);
        uint32_t bbase = (uint32_t)__cvta_generic_to_shared(Bs + buf * BBUFW);
#pragma unroll
        for (int i = 0; i < 4; i++) {
            int q = tid + i * 256;
            int row = q >> 3, c8 = (q & 7) * 8;
            cp16(abase + (row * AST + c8) * 2, A + (size_t)(by * GBM + row) * Kd + k0 + c8);
        }
#pragma unroll
        for (int i = 0; i < 8; i++) {
            int q = tid + i * 256;
            int row = q >> 5, n8 = (q & 31) * 8;
            cp16(bbase + (row * BSTW + n8) * 2, W + (size_t)(k0 + row) * N + bx * WBN + n8);
        }
        asm volatile("cp.async.commit_group;\n");
    };

    issue_tile(0, 0);
    if (ntiles > 1) issue_tile(1, 1);
    for (int t = 0; t < ntiles; t++) {
        if (t + 2 < ntiles) {
            issue_tile(t + 2, (t + 2) & 3);
            asm volatile("cp.async.wait_group 2;\n");
        } else if (t + 1 < ntiles) {
            asm volatile("cp.async.wait_group 1;\n");
        } else {
            asm volatile("cp.async.wait_group 0;\n");
        }
        __syncthreads();
        int buf = t & 3;
        uint32_t Ab = (uint32_t)__cvta_generic_to_shared(As + buf * ABUFH);
        uint32_t Bb = (uint32_t)__cvta_generic_to_shared(Bs + buf * BBUFW);
        uint32_t a_off = Ab + ((warp_m * 64 + lm) * AST + lk) * 2;
#pragma unroll
        for (int ks = 0; ks < GBK / 16; ks++) {
            uint32_t a[4][4], b[8][2];
#pragma unroll
            for (int mi = 0; mi < 4; mi++)
                ldsm_x4(a[mi], a_off + (mi * 16 * AST + ks * 16) * 2);
#pragma unroll
            for (int ni = 0; ni < 8; ni += 2) {
                uint32_t b4[4];
                ldsm_x4t(b4, Bb + ((ks * 16 + vrow) * BSTW + warp_n * 64 + ni * 8 + vcol) * 2);
                b[ni][0] = b4[0]; b[ni][1] = b4[1];
                b[ni + 1][0] = b4[2]; b[ni + 1][1] = b4[3];
            }
#pragma unroll
            for (int mi = 0; mi < 4; mi++)
#pragma unroll
                for (int ni = 0; ni < 8; ni++)
                    mma_f16(c[mi][ni], a[mi], b[ni][0], b[ni][1]);
        }
    }

#pragma unroll
    for (int mi = 0; mi < 4; mi++) {
        int m0 = by * GBM + warp_m * 64 + mi * 16 + g;
#pragma unroll
        for (int ni = 0; ni < 8; ni++) {
            int n0 = bx * WBN + warp_n * 64 + ni * 8 + 2 * tg;
            float b0 = bias[n0], b1 = bias[n0 + 1];
#pragma unroll
            for (int half = 0; half < 2; half++) {
                int m = m0 + half * 8;
                float v0 = c[mi][ni][half * 2 + 0] + b0;
                float v1 = c[mi][ni][half * 2 + 1] + b1;
                if (GELU) { v0 = gelu_tanh(v0); v1 = gelu_tanh(v1); }
                *(__half2*)(C + (size_t)m * N + n0) = __floats2half2_rn(v0, v1);
            }
        }
    }
}

// ---------------- FP16 MMA flash attention v4 (unchanged) --------------------
constexpr int SATT = 72;
constexpr int NQB = CK / 128;   // 16
__global__ __launch_bounds__(256) void attn_kernel(const __half* __restrict__ qkv,
                                                   __half* __restrict__ o) {
    const int pairi = blockIdx.x, h = blockIdx.y, b = blockIdx.z;
    const int tid = threadIdx.x;
    const int w = tid >> 5, lane = tid & 31;
    const int g = lane >> 2, tg = lane & 3;
    const int lm = (lane & 7) + ((lane >> 3) & 1) * 8;
    const int lk = ((lane >> 4) & 1) * 8;

    __shared__ __half KV[6][64 * SATT];
    uint32_t base[6];
#pragma unroll
    for (int i = 0; i < 6; i++) base[i] = (uint32_t)__cvta_generic_to_shared(KV[i]);

    const int srow = (lane & 7) + ((lane >> 4) & 1) * 8;
    const int scol = ((lane >> 3) & 1) * 8;
    const int vrow = (lane & 7) + ((lane >> 3) & 1) * 8;
    const int vcol = ((lane >> 4) & 1) * 8;

    const __half2 sc8 = __float2half2_rn(0.125f);

    for (int s = 0; s < 2; s++) {
        const int qb = (s == 0) ? pairi : (NQB - 1 - pairi);

        __syncthreads();
#pragma unroll
        for (int i = 0; i < 4; i++) {
            int q = tid + i * 256;
            int r = q >> 3, c8 = (q & 7) * 8;
            const __half* src = qkv + ((size_t)(b * CK + qb * 128 + r)) * (3 * CD) + h * 64 + c8;
            uint4 u = *(const uint4*)src;
            __half2* hp = (__half2*)&u;
#pragma unroll
            for (int j = 0; j < 4; j++) hp[j] = __hmul2(hp[j], sc8);
            *(uint4*)&KV[0][r * SATT + c8] = u;
        }
        __syncthreads();
        uint32_t qf[4][4];
#pragma unroll
        for (int ks = 0; ks < 4; ks++)
            ldsm_x4(qf[ks], base[0] + ((w * 16 + lm) * SATT + ks * 16 + lk) * 2);
        __syncthreads();

        float of[8][4];
#pragma unroll
        for (int ni = 0; ni < 8; ni++)
#pragma unroll
            for (int r = 0; r < 4; r++) of[ni][r] = 0.f;
        float mi0 = -1e30f, mi1 = -1e30f, li0 = 0.f, li1 = 0.f;

        const int nt = 2 * qb + 2;
        const int rowg0 = qb * 128 + w * 16 + g;
        const int rowg1 = rowg0 + 8;

        auto issue = [&](int kt, int buf) {
            uint32_t kb = base[buf];
            uint32_t vb = base[3 + buf];
#pragma unroll
            for (int i = 0; i < 2; i++) {
                int q = tid + i * 256;
                int r = q >> 3, c8 = (q & 7) * 8;
                const __half* kbp = qkv + ((size_t)(b * CK + kt * 64 + r)) * (3 * CD) + CD + h * 64 + c8;
                cp16(kb + (r * SATT + c8) * 2, kbp);
                cp16(vb + (r * SATT + c8) * 2, kbp + CD);
            }
            asm volatile("cp.async.commit_group;\n");
        };

        issue(0, 0);
        for (int kt = 0; kt < nt; kt++) {
            if (kt + 1 < nt) {
                issue(kt + 1, (kt + 1) % 3);
                asm volatile("cp.async.wait_group 1;\n");
            } else {
                asm volatile("cp.async.wait_group 0;\n");
            }
            __syncthreads();
            uint32_t ksb = base[kt % 3];
            uint32_t vsb = base[3 + (kt % 3)];

            float sf[8][4];
#pragma unroll
            for (int ni = 0; ni < 8; ni++)
#pragma unroll
                for (int r = 0; r < 4; r++) sf[ni][r] = 0.f;
#pragma unroll
            for (int ks = 0; ks < 4; ks++) {
#pragma unroll
                for (int ni = 0; ni < 8; ni += 2) {
                    uint32_t b4[4];
                    ldsm_x4(b4, ksb + ((ni * 8 + srow) * SATT + ks * 16 + scol) * 2);
                    mma_f16(sf[ni],     qf[ks], b4[0], b4[1]);
                    mma_f16(sf[ni + 1], qf[ks], b4[2], b4[3]);
                }
            }

            if (kt >= 2 * qb) {
                int cbase = kt * 64;
#pragma unroll
                for (int ni = 0; ni < 8; ni++) {
                    int c0 = cbase + ni * 8 + 2 * tg, c1 = c0 + 1;
                    if (c0 > rowg0) sf[ni][0] = -1e30f;
                    if (c1 > rowg0) sf[ni][1] = -1e30f;
                    if (c0 > rowg1) sf[ni][2] = -1e30f;
                    if (c1 > rowg1) sf[ni][3] = -1e30f;
                }
            }

            float m0 = -1e30f, m1 = -1e30f;
#pragma unroll
            for (int ni = 0; ni < 8; ni++) {
                m0 = fmaxf(m0, fmaxf(sf[ni][0], sf[ni][1]));
                m1 = fmaxf(m1, fmaxf(sf[ni][2], sf[ni][3]));
            }
            m0 = fmaxf(m0, __shfl_xor_sync(0xffffffffu, m0, 1));
            m0 = fmaxf(m0, __shfl_xor_sync(0xffffffffu, m0, 2));
            m1 = fmaxf(m1, __shfl_xor_sync(0xffffffffu, m1, 1));
            m1 = fmaxf(m1, __shfl_xor_sync(0xffffffffu, m1, 2));
            float nm0 = fmaxf(mi0, m0), nm1 = fmaxf(mi1, m1);
            float co0 = __expf(mi0 - nm0), co1 = __expf(mi1 - nm1);
            float rs0 = 0.f, rs1 = 0.f;
#pragma unroll
            for (int ni = 0; ni < 8; ni++) {
                sf[ni][0] = __expf(sf[ni][0] - nm0);
                sf[ni][1] = __expf(sf[ni][1] - nm0);
                sf[ni][2] = __expf(sf[ni][2] - nm1);
                sf[ni][3] = __expf(sf[ni][3] - nm1);
                rs0 += sf[ni][0] + sf[ni][1];
                rs1 += sf[ni][2] + sf[ni][3];
            }
            rs0 += __shfl_xor_sync(0xffffffffu, rs0, 1);
            rs0 += __shfl_xor_sync(0xffffffffu, rs0, 2);
            rs1 += __shfl_xor_sync(0xffffffffu, rs1, 1);
            rs1 += __shfl_xor_sync(0xffffffffu, rs1, 2);
            li0 = li0 * co0 + rs0;
            li1 = li1 * co1 + rs1;
            mi0 = nm0; mi1 = nm1;
#pragma unroll
            for (int ni = 0; ni < 8; ni++) {
                of[ni][0] *= co0; of[ni][1] *= co0;
                of[ni][2] *= co1; of[ni][3] *= co1;
            }

#pragma unroll
            for (int js = 0; js < 4; js++) {
                uint32_t a[4];
                a[0] = pack_h2(sf[2 * js][0], sf[2 * js][1]);
                a[1] = pack_h2(sf[2 * js][2], sf[2 * js][3]);
                a[2] = pack_h2(sf[2 * js + 1][0], sf[2 * js + 1][1]);
                a[3] = pack_h2(sf[2 * js + 1][2], sf[2 * js + 1][3]);
#pragma unroll
                for (int ni = 0; ni < 8; ni += 2) {
                    uint32_t b4[4];
                    ldsm_x4t(b4, vsb + ((js * 16 + vrow) * SATT + (ni + (vcol >> 3)) * 8) * 2);
                    mma_f16(of[ni],     a, b4[0], b4[1]);
                    mma_f16(of[ni + 1], a, b4[2], b4[3]);
                }
            }
        }

        float il0 = 1.f / li0, il1 = 1.f / li1;
#pragma unroll
        for (int ni = 0; ni < 8; ni++) {
            int col = h * 64 + ni * 8 + 2 * tg;
            *(__half2*)(o + ((size_t)(b * CK + rowg0)) * CD + col) =
                __floats2half2_rn(of[ni][0] * il0, of[ni][1] * il0);
            *(__half2*)(o + ((size_t)(b * CK + rowg1)) * CD + col) =
                __floats2half2_rn(of[ni][2] * il1, of[ni][3] * il1);
        }
    }
}

// ---------------- output assembly (copy + gated scatter + idx/logits tail) ---
__global__ void outfuse_kernel(const float* __restrict__ x,
                               const float* __restrict__ h,
                               const int* __restrict__ inv,
                               const float* __restrict__ gate,
                               const int* __restrict__ idx,
                               const float* __restrict__ logits,
                               float* __restrict__ out, int has_tail) {
    int row = blockIdx.x;
    int b = row >> 12;
    int pos = inv[row];
    const float4* src = (const float4*)(x + (size_t)row * CD);
    float4* dst = (float4*)(out + (size_t)row * CD);
    float4 v = src[threadIdx.x];
    if (pos >= 0) {
        float gval = gate[b * CK + pos];
        const float4* hp = (const float4*)(h + (size_t)(b * CK + pos) * CD);
        float4 hv = hp[threadIdx.x];
        v.x += hv.x * gval; v.y += hv.y * gval;
        v.z += hv.z * gval; v.w += hv.w * gval;
    }
    dst[threadIdx.x] = v;
    if (has_tail) {
        if (threadIdx.x == 0 && row < CB * CK)
            out[BTD + row] = (float)idx[row];
        if (threadIdx.x == 1)
            out[BTD + CB * CK + row] = logits[row];
    }
}

// ---------------- launch -----------------------------------------------------
extern "C" void kernel_launch(void* const* d_in, const int* in_sizes, int n_in,
                              void* d_out, int out_size) {
    const float* x         = (const float*)d_in[0];
    const float* w_router  = (const float*)d_in[1];
    const float* b_router  = (const float*)d_in[2];
    const float* ln1_scale = (const float*)d_in[3];
    const float* ln1_bias  = (const float*)d_in[4];
    const float* w_qkv     = (const float*)d_in[5];
    const float* b_qkv     = (const float*)d_in[6];
    const float* w_o       = (const float*)d_in[7];
    const float* b_o       = (const float*)d_in[8];
    const float* ln2_scale = (const float*)d_in[9];
    const float* ln2_bias  = (const float*)d_in[10];
    const float* w1        = (const float*)d_in[11];
    const float* b1        = (const float*)d_in[12];
    const float* w2        = (const float*)d_in[13];
    const float* b2        = (const float*)d_in[14];
    float* out = (float*)d_out;

    float *logits, *gate, *h;
    int *sel, *idxp, *invp;
    __half *lnh, *qkvh, *attnh, *midh, *wth;
    cudaGetSymbolAddress((void**)&logits, g_logits);
    cudaGetSymbolAddress((void**)&sel, g_sel);
    cudaGetSymbolAddress((void**)&idxp, g_idx);
    cudaGetSymbolAddress((void**)&invp, g_inv);
    cudaGetSymbolAddress((void**)&gate, g_gate);
    cudaGetSymbolAddress((void**)&h, g_h);
    cudaGetSymbolAddress((void**)&lnh, g_lnh);
    cudaGetSymbolAddress((void**)&qkvh, g_qkvh);
    cudaGetSymbolAddress((void**)&attnh, g_attnh);
    cudaGetSymbolAddress((void**)&midh, g_midh);
    cudaGetSymbolAddress((void**)&wth, g_wth);

    cudaFuncSetAttribute(tgemm_kernel,
                         cudaFuncAttributeMaxDynamicSharedMemorySize, (int)TGEMM_SMEM);
    cudaFuncSetAttribute(tgemm_wide<false>,
                         cudaFuncAttributeMaxDynamicSharedMemorySize, (int)TGEMW_SMEM);
    cudaFuncSetAttribute(tgemm_wide<true>,
                         cudaFuncAttributeMaxDynamicSharedMemorySize, (int)TGEMW_SMEM);

    // 0. WQKV conversion + router (concurrent)
    cvtq_router_kernel<<<QCVT_BLOCKS + ROUTER_BLOCKS, 256>>>(
        w_qkv, wth, x, w_router, b_router, logits);

    // 1-2. top-K
    rank_kernel<<<CB * 64, 256>>>(logits, sel);
    compact_kernel<<<CB, 1024>>>(logits, sel, idxp, invp, gate);

    // 3. fused gather+LN1(layer0) + remaining weight conversion (concurrent)
    gatherln_cvt_kernel<<<GLN_BLOCKS + RWCVT_BLOCKS, 256>>>(
        x, idxp, ln1_scale, ln1_bias, h, lnh, w_o, w1, w2, wth);

    // 4. transformer blocks
    for (int l = 0; l < CL; l++) {
        if (l > 0)
            layernorm_kernel<<<BK_ROWS / 8, 256>>>(h, lnh, ln1_scale + l * CD, ln1_bias + l * CD);
        tgemm_wide<false><<<dim3(3 * CD / WBN, BK_ROWS / GBM), 256, TGEMW_SMEM>>>(
            lnh, wth + WQKV_OFF + (size_t)l * CD * 3 * CD, b_qkv + l * 3 * CD,
            qkvh, BK_ROWS, 3 * CD, CD);
        attn_kernel<<<dim3(NQB / 2, CH, CB), 256>>>(qkvh, attnh);
        tgemm_kernel<<<dim3(CD / GBN, BK_ROWS / GBM), 256, TGEMM_SMEM>>>(
            attnh, wth + WO_OFF + (size_t)l * CD * CD, b_o + l * CD, h, h,
            BK_ROWS, CD, CD);
        layernorm_kernel<<<BK_ROWS / 8, 256>>>(h, lnh, ln2_scale + l * CD, ln2_bias + l * CD);
        tgemm_wide<true><<<dim3(CF / WBN, BK_ROWS / GBM), 256, TGEMW_SMEM>>>(
            lnh, wth + W1_OFF + (size_t)l * CD * CF, b1 + l * CF,
            midh, BK_ROWS, CF, CD);
        tgemm_kernel<<<dim3(CD / GBN, BK_ROWS / GBM), 256, TGEMM_SMEM>>>(
            midh, wth + W2_OFF + (size_t)l * CF * CD, b2 + l * CD, h, h,
            BK_ROWS, CD, CF);
    }

    // 5. assemble output: total + idx + logits in one kernel
    int has_tail = ((size_t)out_size >= BTD + CB * CK + CB * CT) ? 1 : 0;
    outfuse_kernel<<<CB * CT, 256>>>(x, h, invp, gate, idxp, logits, out, has_tail);
}